// round 5
// baseline (speedup 1.0000x reference)
#include <cuda_runtime.h>

// GCN: 250K nodes, 4M edges, F 1->16->16->4.
// edge_index arrives as INT32 (JAX x64 disabled downgrades int64 -> int32).
// Pipeline: count-by-target -> exclusive scan -> place (CSR by target) ->
// layer1 scalar gather -> fused layer2+head gather.
// Layer 1 aggregates a scalar (F_in=1, W1 applied post-aggregation).
// Layer 2 gathers {agg1, dinv} (8B/edge) and recomputes the 16-dim relu
// vector in registers (cheaper than gathering 64B/edge).

static constexpr int NN = 250000;
static constexpr int NE = 4000000;
static constexpr int SCAN_B = 1024;
static constexpr int NB = (NN + SCAN_B - 1) / SCAN_B;  // 245

__device__ int    g_cnt[NN];     // edge count per target (excl. self-loop)
__device__ int    g_fill[NN];    // placement cursors
__device__ int    g_off[NN];     // CSR offsets (exclusive scan of cnt)
__device__ int    g_bsum[NB];    // block partial sums for scan
__device__ float  g_dinv[NN];    // 1/sqrt(deg), deg = cnt+1
__device__ float  g_p[NN];       // x[n] * dinv[n]
__device__ float2 g_node1[NN];   // {agg1[n], dinv[n]}
__device__ int    g_srcs[NE];    // CSR: source node per slot (grouped by target)

__global__ void k_init(int N) {
    int n = blockIdx.x * blockDim.x + threadIdx.x;
    if (n < N) { g_cnt[n] = 0; g_fill[n] = 0; }
}

// Histogram over targets only (second row of edge_index).
__global__ void k_count(const int* __restrict__ col, int E) {
    int e = blockIdx.x * blockDim.x + threadIdx.x;
    if (e < E) atomicAdd(&g_cnt[col[e]], 1);
}

// Per-1024-chunk inclusive->exclusive scan; also computes dinv from deg=cnt+1.
__global__ void k_scan_local(int N) {
    __shared__ int s[SCAN_B];
    int t = threadIdx.x;
    int idx = blockIdx.x * SCAN_B + t;
    int v = (idx < N) ? g_cnt[idx] : 0;
    if (idx < N) g_dinv[idx] = rsqrtf((float)(v + 1));
    s[t] = v;
    __syncthreads();
    #pragma unroll
    for (int d = 1; d < SCAN_B; d <<= 1) {
        int a = (t >= d) ? s[t - d] : 0;
        __syncthreads();
        s[t] += a;
        __syncthreads();
    }
    if (idx < N) g_off[idx] = s[t] - v;  // exclusive
    if (t == SCAN_B - 1) g_bsum[blockIdx.x] = s[t];
}

// Single-block exclusive scan over the (<=256) block sums.
__global__ void k_scan_bsum() {
    __shared__ int s[256];
    int t = threadIdx.x;
    int v = (t < NB) ? g_bsum[t] : 0;
    s[t] = v;
    __syncthreads();
    #pragma unroll
    for (int d = 1; d < 256; d <<= 1) {
        int a = (t >= d) ? s[t - d] : 0;
        __syncthreads();
        s[t] += a;
        __syncthreads();
    }
    if (t < NB) g_bsum[t] = s[t] - v;
}

__global__ void k_addback_p(const float* __restrict__ x, int N) {
    int n = blockIdx.x * blockDim.x + threadIdx.x;
    if (n >= N) return;
    g_off[n] += g_bsum[n / SCAN_B];
    g_p[n] = x[n] * g_dinv[n];
}

// Scatter sources into CSR slots grouped by target.
__global__ void k_place(const int* __restrict__ row, const int* __restrict__ col, int E) {
    int e = blockIdx.x * blockDim.x + threadIdx.x;
    if (e >= E) return;
    int c = col[e];
    int pos = g_off[c] + atomicAdd(&g_fill[c], 1);
    g_srcs[pos] = row[e];
}

// Layer 1: agg1[n] = dinv[n] * (p[n] + sum_{r in N(n)} p[r]),  p = x * dinv.
__global__ void k_layer1(int N) {
    int n = blockIdx.x * blockDim.x + threadIdx.x;
    if (n >= N) return;
    float dn = g_dinv[n];
    float acc = g_p[n];  // self-loop term: (x[n]*dinv[n]) * dinv[n]
    int o = g_off[n];
    int cnt = g_cnt[n];
    for (int i = 0; i < cnt; i++)
        acc += g_p[g_srcs[o + i]];
    g_node1[n] = make_float2(acc * dn, dn);
}

// Layer 2 aggregation + W2/b2/relu + Wfc/bfc head, fused; writes final output.
__global__ void k_layer2_out(const float* __restrict__ W1, const float* __restrict__ b1,
                             const float* __restrict__ W2, const float* __restrict__ b2,
                             const float* __restrict__ Wfc, const float* __restrict__ bfc,
                             float* __restrict__ out, int N) {
    __shared__ float sW1[16], sb1[16], sW2[256], sb2[16], sWfc[64], sbfc[4];
    int t = threadIdx.x;
    if (t < 16) { sW1[t] = W1[t]; sb1[t] = b1[t]; sb2[t] = b2[t]; }
    if (t < 256) sW2[t] = W2[t];
    if (t < 64)  sWfc[t] = Wfc[t];
    if (t < 4)   sbfc[t] = bfc[t];
    __syncthreads();

    int n = blockIdx.x * blockDim.x + t;
    if (n >= N) return;

    float2 self = g_node1[n];
    float acc[16];
    // self-loop: s1(agg1[n]) * dinv[n]  (outer dinv[n] applied after the sum)
    #pragma unroll
    for (int j = 0; j < 16; j++)
        acc[j] = fmaxf(fmaf(self.x, sW1[j], sb1[j]), 0.0f) * self.y;

    int o = g_off[n];
    int cnt = g_cnt[n];
    for (int i = 0; i < cnt; i++) {
        float2 nr = g_node1[g_srcs[o + i]];
        #pragma unroll
        for (int j = 0; j < 16; j++)
            acc[j] += fmaxf(fmaf(nr.x, sW1[j], sb1[j]), 0.0f) * nr.y;
    }

    float dn = self.y;
    float h[16];
    #pragma unroll
    for (int j = 0; j < 16; j++) {
        float v = 0.0f;
        #pragma unroll
        for (int k = 0; k < 16; k++)
            v = fmaf(acc[k], sW2[k * 16 + j], v);
        h[j] = fmaxf(fmaf(v, dn, sb2[j]), 0.0f);
    }

    float oc[4];
    #pragma unroll
    for (int c = 0; c < 4; c++) {
        float v = sbfc[c];
        #pragma unroll
        for (int j = 0; j < 16; j++)
            v = fmaf(h[j], sWfc[j * 4 + c], v);
        oc[c] = v;
    }
    reinterpret_cast<float4*>(out)[n] = make_float4(oc[0], oc[1], oc[2], oc[3]);
}

extern "C" void kernel_launch(void* const* d_in, const int* in_sizes, int n_in,
                              void* d_out, int out_size) {
    const float* x   = (const float*)d_in[0];
    const int*   ei  = (const int*)d_in[1];   // int32! (JAX x64 disabled)
    const float* W1  = (const float*)d_in[2];
    const float* b1  = (const float*)d_in[3];
    const float* W2  = (const float*)d_in[4];
    const float* b2  = (const float*)d_in[5];
    const float* Wfc = (const float*)d_in[6];
    const float* bfc = (const float*)d_in[7];
    (void)n_in; (void)out_size;

    int N = in_sizes[0];       // 250000 (F_in = 1)
    int E = in_sizes[1] / 2;   // 4000000
    const int* row = ei;
    const int* col = ei + E;

    int nbN = (N + 255) / 256;
    int nbE = (E + 255) / 256;
    int nbScan = (N + SCAN_B - 1) / SCAN_B;

    k_init<<<nbN, 256>>>(N);
    k_count<<<nbE, 256>>>(col, E);
    k_scan_local<<<nbScan, SCAN_B>>>(N);
    k_scan_bsum<<<1, 256>>>();
    k_addback_p<<<nbN, 256>>>(x, N);
    k_place<<<nbE, 256>>>(row, col, E);
    k_layer1<<<nbN, 256>>>(N);
    k_layer2_out<<<nbN, 256>>>(W1, b1, W2, b2, Wfc, bfc, (float*)d_out, N);
}